// round 7
// baseline (speedup 1.0000x reference)
#include <cuda_runtime.h>
#include <cuda_bf16.h>
#include <cstdint>

// ---------------- problem constants ----------------
#define Bb 4
#define Ss 2048
#define Ee 768
#define Hh 3
#define Dd 256
#define BHh 12
#define SCALE 0.022097086912079608f   // 1/sqrt(2048)

#define NE (8192 * 768)
#define EE (768 * 768)

// ---------------- scratch (device globals; no cudaMalloc allowed) ----------------
__device__ __align__(16) __nv_bfloat16 g_Xhi[3][NE];
__device__ __align__(16) __nv_bfloat16 g_Xlo[3][NE];
__device__ __align__(16) __nv_bfloat16 g_Wthi[3][EE];   // W^T: [n=h*256+d][k=e]
__device__ __align__(16) __nv_bfloat16 g_Wtlo[3][EE];
__device__ __align__(16) __nv_bfloat16 g_Wohi[EE];      // Wo^T: [n=eout][k=ein]
__device__ __align__(16) __nv_bfloat16 g_Wolo[EE];
__device__ __align__(16) __nv_bfloat16 g_Qhi[BHh * Ss * Dd];  // [z][s][d]
__device__ __align__(16) __nv_bfloat16 g_Qlo[BHh * Ss * Dd];
__device__ __align__(16) __nv_bfloat16 g_Khi[BHh * Ss * Dd];
__device__ __align__(16) __nv_bfloat16 g_Klo[BHh * Ss * Dd];
__device__ __align__(16) __nv_bfloat16 g_Vthi[BHh * Dd * Ss]; // [z][d][s]
__device__ __align__(16) __nv_bfloat16 g_Vtlo[BHh * Dd * Ss];
__device__ float g_scores[(size_t)BHh * Ss * Ss];
__device__ __align__(16) __nv_bfloat16 g_Phi[(size_t)BHh * Ss * Ss];
__device__ __align__(16) __nv_bfloat16 g_Plo[(size_t)BHh * Ss * Ss];
__device__ __align__(16) __nv_bfloat16 g_Chi[NE];
__device__ __align__(16) __nv_bfloat16 g_Clo[NE];

// ---------------- helpers ----------------
__device__ __forceinline__ uint32_t smem_u32(const void* p) {
    uint32_t a;
    asm("{ .reg .u64 t; cvta.to.shared.u64 t, %1; cvt.u32.u64 %0, t; }" : "=r"(a) : "l"(p));
    return a;
}
__device__ __forceinline__ void ldsm4(uint32_t r[4], uint32_t addr) {
    asm volatile("ldmatrix.sync.aligned.m8n8.x4.shared.b16 {%0,%1,%2,%3}, [%4];"
                 : "=r"(r[0]), "=r"(r[1]), "=r"(r[2]), "=r"(r[3]) : "r"(addr));
}
__device__ __forceinline__ void mma16816(float c[4], const uint32_t a[4], uint32_t b0, uint32_t b1) {
    asm volatile("mma.sync.aligned.m16n8k16.row.col.f32.bf16.bf16.f32 "
                 "{%0,%1,%2,%3}, {%4,%5,%6,%7}, {%8,%9}, {%0,%1,%2,%3};"
                 : "+f"(c[0]), "+f"(c[1]), "+f"(c[2]), "+f"(c[3])
                 : "r"(a[0]), "r"(a[1]), "r"(a[2]), "r"(a[3]), "r"(b0), "r"(b1));
}
__device__ __forceinline__ void split2(float x, __nv_bfloat16& hi, __nv_bfloat16& lo) {
    hi = __float2bfloat16(x);
    lo = __float2bfloat16(x - __bfloat162float(hi));
}

// ---------------- conversion kernels ----------------
__global__ __launch_bounds__(256) void conv_inputs(const float* __restrict__ Xk,
                                                   const float* __restrict__ Xv,
                                                   const float* __restrict__ Xq) {
    int i = blockIdx.x * blockDim.x + threadIdx.x;
    if (i >= NE) return;
    __nv_bfloat16 hi, lo;
    split2(Xk[i], hi, lo); g_Xhi[0][i] = hi; g_Xlo[0][i] = lo;
    split2(Xv[i], hi, lo); g_Xhi[1][i] = hi; g_Xlo[1][i] = lo;
    split2(Xq[i], hi, lo); g_Xhi[2][i] = hi; g_Xlo[2][i] = lo;
}

__global__ __launch_bounds__(256) void conv_weights(const float* __restrict__ WK,
                                                    const float* __restrict__ WV,
                                                    const float* __restrict__ WQ,
                                                    const float* __restrict__ Wo) {
    int i = blockIdx.x * blockDim.x + threadIdx.x;
    if (i >= EE) return;
    int h = i / (Ee * Dd);
    int r = i % (Ee * Dd);
    int e = r / Dd;
    int d = r % Dd;
    int dst = (h * Dd + d) * Ee + e;
    __nv_bfloat16 hi, lo;
    split2(WK[i], hi, lo); g_Wthi[0][dst] = hi; g_Wtlo[0][dst] = lo;
    split2(WV[i], hi, lo); g_Wthi[1][dst] = hi; g_Wtlo[1][dst] = lo;
    split2(WQ[i], hi, lo); g_Wthi[2][dst] = hi; g_Wtlo[2][dst] = lo;
    int k = i / Ee, n = i % Ee;
    split2(Wo[i], hi, lo); g_Wohi[n * Ee + k] = hi; g_Wolo[n * Ee + k] = lo;
}

// ---------------- mma.sync GEMM core: BK=64, 3-stage dynamic-smem pipeline ----------------
// 128x128 block tile, BK=64, 256 threads, 8 warps (2M x 4N), warp tile 64x32.
// A row-major [m][k] (lda), B NT row-major [n][k] (ldb).
// smem rows: 64 bf16 (128B) padded to 144B. Stage = 36864 B; 3 stages = 110592 B.
struct Seg { const __nv_bfloat16* A; const __nv_bfloat16* B; int klen; };

#define ROWB 144
#define HALF_STAGE (128 * ROWB)          // 18432
#define STAGE_BYTES (2 * HALF_STAGE)     // 36864
#define SMEM_TOTAL (3 * STAGE_BYTES)     // 110592

__device__ __forceinline__ void load_tiles(uint32_t st,
                                           const __nv_bfloat16* __restrict__ A, int lda,
                                           const __nv_bfloat16* __restrict__ B, int ldb,
                                           int k0) {
    int tid = threadIdx.x;
#pragma unroll
    for (int c = 0; c < 4; c++) {
        int idx = tid + c * 256;           // 1024 chunks: 128 rows x 8 chunks
        int row = idx >> 3, ch = idx & 7;
        const void* srcA = A + (size_t)row * lda + k0 + ch * 8;
        asm volatile("cp.async.cg.shared.global [%0], [%1], 16;"
                     :: "r"(st + row * ROWB + ch * 16), "l"(srcA));
    }
#pragma unroll
    for (int c = 0; c < 4; c++) {
        int idx = tid + c * 256;
        int row = idx >> 3, ch = idx & 7;
        const void* srcB = B + (size_t)row * ldb + k0 + ch * 8;
        asm volatile("cp.async.cg.shared.global [%0], [%1], 16;"
                     :: "r"(st + HALF_STAGE + row * ROWB + ch * 16), "l"(srcB));
    }
    asm volatile("cp.async.commit_group;");
}

__device__ __forceinline__ void compute_stage(uint32_t st, float acc[4][4][4],
                                              int wm, int wn, int lane) {
    uint32_t sA = st, sB = st + HALF_STAGE;
#pragma unroll
    for (int ks = 0; ks < 4; ks++) {
        uint32_t a[4][4];
#pragma unroll
        for (int mi = 0; mi < 4; mi++) {
            uint32_t addr = sA + (wm + mi * 16 + (lane & 15)) * ROWB + ks * 32 + (lane >> 4) * 16;
            ldsm4(a[mi], addr);
        }
        uint32_t b[2][4];
#pragma unroll
        for (int nj = 0; nj < 2; nj++) {
            uint32_t addr = sB + (wn + nj * 16 + (lane & 7) + ((lane >> 4) & 1) * 8) * ROWB +
                            ks * 32 + ((lane >> 3) & 1) * 16;
            ldsm4(b[nj], addr);
        }
#pragma unroll
        for (int mi = 0; mi < 4; mi++)
#pragma unroll
            for (int ni = 0; ni < 4; ni++)
                mma16816(acc[mi][ni], a[mi], b[ni >> 1][(ni & 1) * 2], b[ni >> 1][(ni & 1) * 2 + 1]);
    }
}

__device__ __forceinline__ void gemm_run(const Seg seg[3], int lda, int ldb,
                                         uint32_t sbase, float acc[4][4][4],
                                         int wm, int wn, int lane) {
    int total = (seg[0].klen + seg[1].klen + seg[2].klen) >> 6;
    int si = 0, k = 0;
#pragma unroll
    for (int p = 0; p < 2; p++) {          // total >= 4 always
        load_tiles(sbase + p * STAGE_BYTES, seg[si].A, lda, seg[si].B, ldb, k);
        k += 64;
        if (k >= seg[si].klen) { k = 0; si++; }
    }
    int bufs[3] = { 0, STAGE_BYTES, 2 * STAGE_BYTES };
    int cur = 0;
    for (int t = 0; t < total; t++) {
        if (t + 2 < total) {
            int nxt = cur + 2; if (nxt >= 3) nxt -= 3;
            load_tiles(sbase + bufs[nxt], seg[si].A, lda, seg[si].B, ldb, k);
            k += 64;
            if (k >= seg[si].klen) { k = 0; si++; }
            asm volatile("cp.async.wait_group 2;");
        } else if (t + 1 < total) {
            asm volatile("cp.async.wait_group 1;");
        } else {
            asm volatile("cp.async.wait_group 0;");
        }
        __syncthreads();
        compute_stage(sbase + bufs[cur], acc, wm, wn, lane);
        __syncthreads();
        cur++; if (cur >= 3) cur = 0;
    }
}

// ---------------- projections ----------------
__global__ __launch_bounds__(256, 2) void mma_proj(int m) {
    extern __shared__ __align__(16) char smd[];
    int tid = threadIdx.x, lane = tid & 31, w = tid >> 5;
    int wm = (w & 1) * 64, wn = (w >> 1) * 32;
    uint32_t sbase = smem_u32(smd);
    int rowBase = blockIdx.y * 128, colBase = blockIdx.x * 128;
    float acc[4][4][4] = {};
    Seg seg[3] = {
        { g_Xhi[m] + (size_t)rowBase * Ee, g_Wthi[m] + (size_t)colBase * Ee, Ee },
        { g_Xlo[m] + (size_t)rowBase * Ee, g_Wthi[m] + (size_t)colBase * Ee, Ee },
        { g_Xhi[m] + (size_t)rowBase * Ee, g_Wtlo[m] + (size_t)colBase * Ee, Ee } };
    gemm_run(seg, Ee, Ee, sbase, acc, wm, wn, lane);

    int lr = lane >> 2, lc = (lane & 3) * 2;
#pragma unroll
    for (int mi = 0; mi < 4; mi++)
#pragma unroll
        for (int ni = 0; ni < 4; ni++)
#pragma unroll
            for (int half = 0; half < 2; half++) {
                int gr = rowBase + wm + mi * 16 + lr + half * 8;
                int b = gr >> 11, sI = gr & 2047;
                int col = colBase + wn + ni * 8 + lc;
                int h = col >> 8, d = col & 255;
                int z = b * Hh + h;
                float v0 = acc[mi][ni][half * 2], v1 = acc[mi][ni][half * 2 + 1];
                __nv_bfloat16 h0, l0, h1, l1;
                split2(v0, h0, l0);
                split2(v1, h1, l1);
                if (m == 1) {
                    size_t d0 = ((size_t)z * Dd + d) * Ss + sI;
                    size_t d1 = ((size_t)z * Dd + d + 1) * Ss + sI;
                    g_Vthi[d0] = h0; g_Vtlo[d0] = l0;
                    g_Vthi[d1] = h1; g_Vtlo[d1] = l1;
                } else {
                    size_t dst = ((size_t)z * Ss + sI) * Dd + d;
                    if (m == 0) { g_Khi[dst] = h0; g_Klo[dst] = l0;
                                  g_Khi[dst + 1] = h1; g_Klo[dst + 1] = l1; }
                    else        { g_Qhi[dst] = h0; g_Qlo[dst] = l0;
                                  g_Qhi[dst + 1] = h1; g_Qlo[dst + 1] = l1; }
                }
            }
}

// ---------------- scores = Q K^T * SCALE (causal tile skip) ----------------
__global__ __launch_bounds__(256, 2) void mma_scores() {
    if (blockIdx.x > blockIdx.y) return;
    extern __shared__ __align__(16) char smd[];
    int tid = threadIdx.x, lane = tid & 31, w = tid >> 5;
    int wm = (w & 1) * 64, wn = (w >> 1) * 32;
    uint32_t sbase = smem_u32(smd);
    int z = blockIdx.z;
    int rowBase = blockIdx.y * 128, colBase = blockIdx.x * 128;
    size_t qo = (size_t)z * Ss * Dd;
    const __nv_bfloat16* Qh = g_Qhi + qo + (size_t)rowBase * Dd;
    const __nv_bfloat16* Ql = g_Qlo + qo + (size_t)rowBase * Dd;
    const __nv_bfloat16* Kh = g_Khi + qo + (size_t)colBase * Dd;
    const __nv_bfloat16* Kl = g_Klo + qo + (size_t)colBase * Dd;
    float acc[4][4][4] = {};
    Seg seg[3] = { { Qh, Kh, Dd }, { Ql, Kh, Dd }, { Qh, Kl, Dd } };
    gemm_run(seg, Dd, Dd, sbase, acc, wm, wn, lane);

    float* C = g_scores + (size_t)z * Ss * Ss;
    int lr = lane >> 2, lc = (lane & 3) * 2;
#pragma unroll
    for (int mi = 0; mi < 4; mi++)
#pragma unroll
        for (int ni = 0; ni < 4; ni++)
#pragma unroll
            for (int half = 0; half < 2; half++) {
                int gr = rowBase + wm + mi * 16 + lr + half * 8;
                int col = colBase + wn + ni * 8 + lc;
                float2 v = make_float2(acc[mi][ni][half * 2] * SCALE,
                                       acc[mi][ni][half * 2 + 1] * SCALE);
                *(float2*)&C[(size_t)gr * Ss + col] = v;
            }
}

// ---------------- causal softmax; single pass, P written only up to Lpad ----------------
__global__ __launch_bounds__(256) void softmax_rows() {
    __shared__ float red[8];
    int gid = blockIdx.x;
    int z = gid >> 11;
    int i = gid & 2047;
    size_t ro = (size_t)z * Ss * Ss + (size_t)i * Ss;
    const float* row = g_scores + ro;
    int L = i + 1;
    int Lpad = ((i >> 7) + 1) << 7;   // = kEnd boundary that mma_pv consumes
    int tid = threadIdx.x;
    float v[8];
#pragma unroll
    for (int s = 0; s < 8; s++) {
        int j = tid + s * 256;
        v[s] = (j < L) ? row[j] : -3.4e38f;
    }
    float mx = v[0];
#pragma unroll
    for (int s = 1; s < 8; s++) mx = fmaxf(mx, v[s]);
#pragma unroll
    for (int o = 16; o; o >>= 1) mx = fmaxf(mx, __shfl_xor_sync(0xffffffffu, mx, o));
    if ((tid & 31) == 0) red[tid >> 5] = mx;
    __syncthreads();
    mx = red[0];
#pragma unroll
    for (int ww = 1; ww < 8; ww++) mx = fmaxf(mx, red[ww]);
    __syncthreads();
    float e[8];
    float sum = 0.f;
#pragma unroll
    for (int s = 0; s < 8; s++) {
        int j = tid + s * 256;
        e[s] = (j < L) ? __expf(v[s] - mx) : 0.0f;
        sum += e[s];
    }
#pragma unroll
    for (int o = 16; o; o >>= 1) sum += __shfl_xor_sync(0xffffffffu, sum, o);
    if ((tid & 31) == 0) red[tid >> 5] = sum;
    __syncthreads();
    sum = red[0];
#pragma unroll
    for (int ww = 1; ww < 8; ww++) sum += red[ww];
    float inv = 1.0f / sum;
#pragma unroll
    for (int s = 0; s < 8; s++) {
        int j = tid + s * 256;
        if (j < Lpad) {
            float p = e[s] * inv;
            __nv_bfloat16 hi, lo;
            split2(p, hi, lo);
            g_Phi[ro + j] = hi;
            g_Plo[ro + j] = lo;
        }
    }
}

// ---------------- Z = P V (causal K-limit) -> concat hi/lo ----------------
__global__ __launch_bounds__(256, 2) void mma_pv() {
    extern __shared__ __align__(16) char smd[];
    int tid = threadIdx.x, lane = tid & 31, w = tid >> 5;
    int wm = (w & 1) * 64, wn = (w >> 1) * 32;
    uint32_t sbase = smem_u32(smd);
    int z = blockIdx.z;
    int rowBase = blockIdx.y * 128, colBase = blockIdx.x * 128;
    int kEnd = rowBase + 128;
    const __nv_bfloat16* Ph = g_Phi + (size_t)z * Ss * Ss + (size_t)rowBase * Ss;
    const __nv_bfloat16* Pl = g_Plo + (size_t)z * Ss * Ss + (size_t)rowBase * Ss;
    const __nv_bfloat16* Vh = g_Vthi + (size_t)z * Dd * Ss + (size_t)colBase * Ss;
    const __nv_bfloat16* Vl = g_Vtlo + (size_t)z * Dd * Ss + (size_t)colBase * Ss;
    float acc[4][4][4] = {};
    Seg seg[3] = { { Ph, Vh, kEnd }, { Pl, Vh, kEnd }, { Ph, Vl, kEnd } };
    gemm_run(seg, Ss, Ss, sbase, acc, wm, wn, lane);

    int b = z / Hh, h = z % Hh;
    int lr = lane >> 2, lc = (lane & 3) * 2;
#pragma unroll
    for (int mi = 0; mi < 4; mi++)
#pragma unroll
        for (int ni = 0; ni < 4; ni++)
#pragma unroll
            for (int half = 0; half < 2; half++) {
                int sI = rowBase + wm + mi * 16 + lr + half * 8;
                int d = colBase + wn + ni * 8 + lc;
                __nv_bfloat16 h0, l0, h1, l1;
                split2(acc[mi][ni][half * 2], h0, l0);
                split2(acc[mi][ni][half * 2 + 1], h1, l1);
                size_t dst = ((size_t)(b * Ss + sI)) * Ee + h * Dd + d;
                g_Chi[dst] = h0; g_Clo[dst] = l0;
                g_Chi[dst + 1] = h1; g_Clo[dst + 1] = l1;
            }
}

// ---------------- out = concat @ Wo + bo ----------------
__global__ __launch_bounds__(256, 2) void mma_out(const float* __restrict__ bo,
                                                  float* __restrict__ out) {
    extern __shared__ __align__(16) char smd[];
    int tid = threadIdx.x, lane = tid & 31, w = tid >> 5;
    int wm = (w & 1) * 64, wn = (w >> 1) * 32;
    uint32_t sbase = smem_u32(smd);
    int rowBase = blockIdx.y * 128, colBase = blockIdx.x * 128;
    float acc[4][4][4] = {};
    Seg seg[3] = {
        { g_Chi + (size_t)rowBase * Ee, g_Wohi + (size_t)colBase * Ee, Ee },
        { g_Clo + (size_t)rowBase * Ee, g_Wohi + (size_t)colBase * Ee, Ee },
        { g_Chi + (size_t)rowBase * Ee, g_Wolo + (size_t)colBase * Ee, Ee } };
    gemm_run(seg, Ee, Ee, sbase, acc, wm, wn, lane);

    int lr = lane >> 2, lc = (lane & 3) * 2;
#pragma unroll
    for (int mi = 0; mi < 4; mi++)
#pragma unroll
        for (int ni = 0; ni < 4; ni++)
#pragma unroll
            for (int half = 0; half < 2; half++) {
                int gr = rowBase + wm + mi * 16 + lr + half * 8;
                int col = colBase + wn + ni * 8 + lc;
                float2 v = make_float2(acc[mi][ni][half * 2] + bo[col],
                                       acc[mi][ni][half * 2 + 1] + bo[col + 1]);
                *(float2*)&out[(size_t)gr * Ee + col] = v;
            }
}

// ---------------- launch ----------------
extern "C" void kernel_launch(void* const* d_in, const int* in_sizes, int n_in,
                              void* d_out, int out_size) {
    const float* Xk = (const float*)d_in[0];
    const float* Xv = (const float*)d_in[1];
    const float* Xq = (const float*)d_in[2];
    const float* WK = (const float*)d_in[3];
    const float* WV = (const float*)d_in[4];
    const float* WQ = (const float*)d_in[5];
    const float* Wo = (const float*)d_in[6];
    const float* bo = (const float*)d_in[7];
    float* out = (float*)d_out;

    // opt-in to >48KB dynamic smem (host-side attribute set; idempotent)
    cudaFuncSetAttribute(mma_proj, cudaFuncAttributeMaxDynamicSharedMemorySize, SMEM_TOTAL);
    cudaFuncSetAttribute(mma_scores, cudaFuncAttributeMaxDynamicSharedMemorySize, SMEM_TOTAL);
    cudaFuncSetAttribute(mma_pv, cudaFuncAttributeMaxDynamicSharedMemorySize, SMEM_TOTAL);
    cudaFuncSetAttribute(mma_out, cudaFuncAttributeMaxDynamicSharedMemorySize, SMEM_TOTAL);

    conv_inputs<<<(NE + 255) / 256, 256>>>(Xk, Xv, Xq);
    conv_weights<<<(EE + 255) / 256, 256>>>(WK, WV, WQ, Wo);

    dim3 gProj(Ee / 128, (Bb * Ss) / 128);     // (6, 64)
    mma_proj<<<gProj, 256, SMEM_TOTAL>>>(0);
    mma_proj<<<gProj, 256, SMEM_TOTAL>>>(1);
    mma_proj<<<gProj, 256, SMEM_TOTAL>>>(2);

    dim3 gSc(Ss / 128, Ss / 128, BHh);         // (16, 16, 12)
    mma_scores<<<gSc, 256, SMEM_TOTAL>>>();

    softmax_rows<<<BHh * Ss, 256>>>();

    dim3 gPv(Dd / 128, Ss / 128, BHh);         // (2, 16, 12)
    mma_pv<<<gPv, 256, SMEM_TOTAL>>>();

    dim3 gOut(Ee / 128, (Bb * Ss) / 128);      // (6, 64)
    mma_out<<<gOut, 256, SMEM_TOTAL>>>(bo, out);
}

// round 8
// speedup vs baseline: 1.1047x; 1.1047x over previous
#include <cuda_runtime.h>
#include <cuda_bf16.h>
#include <cstdint>

// ---------------- problem constants ----------------
#define Bb 4
#define Ss 2048
#define Ee 768
#define Hh 3
#define Dd 256
#define BHh 12
#define SCALE 0.022097086912079608f   // 1/sqrt(2048)

#define NE (8192 * 768)
#define EE (768 * 768)

// ---------------- scratch (device globals; no cudaMalloc allowed) ----------------
__device__ __align__(16) __nv_bfloat16 g_Xhi[3][NE];
__device__ __align__(16) __nv_bfloat16 g_Xlo[3][NE];
__device__ __align__(16) __nv_bfloat16 g_Wthi[3][EE];   // W^T: [n=h*256+d][k=e]
__device__ __align__(16) __nv_bfloat16 g_Wtlo[3][EE];
__device__ __align__(16) __nv_bfloat16 g_Wohi[EE];      // Wo^T: [n=eout][k=ein]
__device__ __align__(16) __nv_bfloat16 g_Wolo[EE];
__device__ __align__(16) __nv_bfloat16 g_Qhi[BHh * Ss * Dd];  // [z][s][d]
__device__ __align__(16) __nv_bfloat16 g_Qlo[BHh * Ss * Dd];
__device__ __align__(16) __nv_bfloat16 g_Khi[BHh * Ss * Dd];
__device__ __align__(16) __nv_bfloat16 g_Klo[BHh * Ss * Dd];
__device__ __align__(16) __nv_bfloat16 g_Vthi[BHh * Dd * Ss]; // [z][d][s]
__device__ __align__(16) __nv_bfloat16 g_Vtlo[BHh * Dd * Ss];
__device__ float g_scores[(size_t)BHh * Ss * Ss];
__device__ __align__(16) __nv_bfloat16 g_Phi[(size_t)BHh * Ss * Ss];
__device__ __align__(16) __nv_bfloat16 g_Plo[(size_t)BHh * Ss * Ss];
__device__ __align__(16) __nv_bfloat16 g_Chi[NE];
__device__ __align__(16) __nv_bfloat16 g_Clo[NE];

// ---------------- helpers ----------------
__device__ __forceinline__ uint32_t smem_u32(const void* p) {
    uint32_t a;
    asm("{ .reg .u64 t; cvta.to.shared.u64 t, %1; cvt.u32.u64 %0, t; }" : "=r"(a) : "l"(p));
    return a;
}
__device__ __forceinline__ void ldsm4(uint32_t r[4], uint32_t addr) {
    asm volatile("ldmatrix.sync.aligned.m8n8.x4.shared.b16 {%0,%1,%2,%3}, [%4];"
                 : "=r"(r[0]), "=r"(r[1]), "=r"(r[2]), "=r"(r[3]) : "r"(addr));
}
__device__ __forceinline__ void mma16816(float c[4], const uint32_t a[4], uint32_t b0, uint32_t b1) {
    asm volatile("mma.sync.aligned.m16n8k16.row.col.f32.bf16.bf16.f32 "
                 "{%0,%1,%2,%3}, {%4,%5,%6,%7}, {%8,%9}, {%0,%1,%2,%3};"
                 : "+f"(c[0]), "+f"(c[1]), "+f"(c[2]), "+f"(c[3])
                 : "r"(a[0]), "r"(a[1]), "r"(a[2]), "r"(a[3]), "r"(b0), "r"(b1));
}
__device__ __forceinline__ void split2(float x, __nv_bfloat16& hi, __nv_bfloat16& lo) {
    hi = __float2bfloat16(x);
    lo = __float2bfloat16(x - __bfloat162float(hi));
}

// ---------------- conversion kernels ----------------
__global__ __launch_bounds__(256) void conv_inputs(const float* __restrict__ Xk,
                                                   const float* __restrict__ Xv,
                                                   const float* __restrict__ Xq) {
    int i = blockIdx.x * blockDim.x + threadIdx.x;
    if (i >= NE) return;
    __nv_bfloat16 hi, lo;
    split2(Xk[i], hi, lo); g_Xhi[0][i] = hi; g_Xlo[0][i] = lo;
    split2(Xv[i], hi, lo); g_Xhi[1][i] = hi; g_Xlo[1][i] = lo;
    split2(Xq[i], hi, lo); g_Xhi[2][i] = hi; g_Xlo[2][i] = lo;
}

__global__ __launch_bounds__(256) void conv_weights(const float* __restrict__ WK,
                                                    const float* __restrict__ WV,
                                                    const float* __restrict__ WQ,
                                                    const float* __restrict__ Wo) {
    int i = blockIdx.x * blockDim.x + threadIdx.x;
    if (i >= EE) return;
    int h = i / (Ee * Dd);
    int r = i % (Ee * Dd);
    int e = r / Dd;
    int d = r % Dd;
    int dst = (h * Dd + d) * Ee + e;
    __nv_bfloat16 hi, lo;
    split2(WK[i], hi, lo); g_Wthi[0][dst] = hi; g_Wtlo[0][dst] = lo;
    split2(WV[i], hi, lo); g_Wthi[1][dst] = hi; g_Wtlo[1][dst] = lo;
    split2(WQ[i], hi, lo); g_Wthi[2][dst] = hi; g_Wtlo[2][dst] = lo;
    int k = i / Ee, n = i % Ee;
    split2(Wo[i], hi, lo); g_Wohi[n * Ee + k] = hi; g_Wolo[n * Ee + k] = lo;
}

// ---------------- mma.sync GEMM core: BK=64, 2-stage dynamic-smem pipeline (R6 proven) ----
// 128x128 block tile, BK=64, 256 threads, 8 warps (2M x 4N), warp tile 64x32.
// A row-major [m][k] (lda), B NT row-major [n][k] (ldb).
// smem rows: 64 bf16 (128B) padded to 144B. Stage = 36864 B; 2 stages = 73728 B.
struct Seg { const __nv_bfloat16* A; const __nv_bfloat16* B; int klen; };

#define ROWB 144
#define HALF_STAGE (128 * ROWB)          // 18432
#define STAGE_BYTES (2 * HALF_STAGE)     // 36864
#define SMEM_TOTAL (2 * STAGE_BYTES)     // 73728

__device__ __forceinline__ void load_tiles(uint32_t st,
                                           const __nv_bfloat16* __restrict__ A, int lda,
                                           const __nv_bfloat16* __restrict__ B, int ldb,
                                           int k0) {
    int tid = threadIdx.x;
#pragma unroll
    for (int c = 0; c < 4; c++) {
        int idx = tid + c * 256;           // 1024 chunks: 128 rows x 8 chunks
        int row = idx >> 3, ch = idx & 7;
        const void* srcA = A + (size_t)row * lda + k0 + ch * 8;
        asm volatile("cp.async.cg.shared.global [%0], [%1], 16;"
                     :: "r"(st + row * ROWB + ch * 16), "l"(srcA));
    }
#pragma unroll
    for (int c = 0; c < 4; c++) {
        int idx = tid + c * 256;
        int row = idx >> 3, ch = idx & 7;
        const void* srcB = B + (size_t)row * ldb + k0 + ch * 8;
        asm volatile("cp.async.cg.shared.global [%0], [%1], 16;"
                     :: "r"(st + HALF_STAGE + row * ROWB + ch * 16), "l"(srcB));
    }
    asm volatile("cp.async.commit_group;");
}

__device__ __forceinline__ void compute_stage(uint32_t st, float acc[4][4][4],
                                              int wm, int wn, int lane) {
    uint32_t sA = st, sB = st + HALF_STAGE;
#pragma unroll
    for (int ks = 0; ks < 4; ks++) {
        uint32_t a[4][4];
#pragma unroll
        for (int mi = 0; mi < 4; mi++) {
            uint32_t addr = sA + (wm + mi * 16 + (lane & 15)) * ROWB + ks * 32 + (lane >> 4) * 16;
            ldsm4(a[mi], addr);
        }
        uint32_t b[2][4];
#pragma unroll
        for (int nj = 0; nj < 2; nj++) {
            uint32_t addr = sB + (wn + nj * 16 + (lane & 7) + ((lane >> 4) & 1) * 8) * ROWB +
                            ks * 32 + ((lane >> 3) & 1) * 16;
            ldsm4(b[nj], addr);
        }
#pragma unroll
        for (int mi = 0; mi < 4; mi++)
#pragma unroll
            for (int ni = 0; ni < 4; ni++)
                mma16816(acc[mi][ni], a[mi], b[ni >> 1][(ni & 1) * 2], b[ni >> 1][(ni & 1) * 2 + 1]);
    }
}

__device__ __forceinline__ void gemm_run(const Seg seg[3], int lda, int ldb,
                                         uint32_t sbase, float acc[4][4][4],
                                         int wm, int wn, int lane) {
    int total = (seg[0].klen + seg[1].klen + seg[2].klen) >> 6;
    int si = 0, k = 0;
    load_tiles(sbase, seg[0].A, lda, seg[0].B, ldb, 0);
    k = 64;
    if (k >= seg[0].klen) { k = 0; si = 1; }
    for (int t = 0; t < total; t++) {
        uint32_t cur = sbase + (t & 1) * STAGE_BYTES;
        if (t + 1 < total) {
            uint32_t nxt = sbase + ((t + 1) & 1) * STAGE_BYTES;
            load_tiles(nxt, seg[si].A, lda, seg[si].B, ldb, k);
            k += 64;
            if (k >= seg[si].klen) { k = 0; si++; }
            asm volatile("cp.async.wait_group 1;");
        } else {
            asm volatile("cp.async.wait_group 0;");
        }
        __syncthreads();
        compute_stage(cur, acc, wm, wn, lane);
        __syncthreads();
    }
}

// ---------------- projections (all 3 fused: blockIdx.z = m) ----------------
__global__ __launch_bounds__(256, 2) void mma_proj() {
    extern __shared__ __align__(16) char smd[];
    int m = blockIdx.z;
    int tid = threadIdx.x, lane = tid & 31, w = tid >> 5;
    int wm = (w & 1) * 64, wn = (w >> 1) * 32;
    uint32_t sbase = smem_u32(smd);
    int rowBase = blockIdx.y * 128, colBase = blockIdx.x * 128;
    float acc[4][4][4] = {};
    Seg seg[3] = {
        { g_Xhi[m] + (size_t)rowBase * Ee, g_Wthi[m] + (size_t)colBase * Ee, Ee },
        { g_Xlo[m] + (size_t)rowBase * Ee, g_Wthi[m] + (size_t)colBase * Ee, Ee },
        { g_Xhi[m] + (size_t)rowBase * Ee, g_Wtlo[m] + (size_t)colBase * Ee, Ee } };
    gemm_run(seg, Ee, Ee, sbase, acc, wm, wn, lane);

    int lr = lane >> 2, lc = (lane & 3) * 2;
#pragma unroll
    for (int mi = 0; mi < 4; mi++)
#pragma unroll
        for (int ni = 0; ni < 4; ni++)
#pragma unroll
            for (int half = 0; half < 2; half++) {
                int gr = rowBase + wm + mi * 16 + lr + half * 8;
                int b = gr >> 11, sI = gr & 2047;
                int col = colBase + wn + ni * 8 + lc;
                int h = col >> 8, d = col & 255;
                int z = b * Hh + h;
                float v0 = acc[mi][ni][half * 2], v1 = acc[mi][ni][half * 2 + 1];
                __nv_bfloat16 h0, l0, h1, l1;
                split2(v0, h0, l0);
                split2(v1, h1, l1);
                if (m == 1) {
                    size_t d0 = ((size_t)z * Dd + d) * Ss + sI;
                    size_t d1 = ((size_t)z * Dd + d + 1) * Ss + sI;
                    g_Vthi[d0] = h0; g_Vtlo[d0] = l0;
                    g_Vthi[d1] = h1; g_Vtlo[d1] = l1;
                } else {
                    size_t dst = ((size_t)z * Ss + sI) * Dd + d;
                    if (m == 0) { g_Khi[dst] = h0; g_Klo[dst] = l0;
                                  g_Khi[dst + 1] = h1; g_Klo[dst + 1] = l1; }
                    else        { g_Qhi[dst] = h0; g_Qlo[dst] = l0;
                                  g_Qhi[dst + 1] = h1; g_Qlo[dst + 1] = l1; }
                }
            }
}

// ---------------- scores = Q K^T * SCALE, compact lower-triangle grid ----------------
// blockIdx.x = t in [0,136) -> (by, bx) with bx <= by
__global__ __launch_bounds__(256, 2) void mma_scores() {
    extern __shared__ __align__(16) char smd[];
    int t = blockIdx.x;
    int by = (int)((sqrtf(8.0f * t + 1.0f) - 1.0f) * 0.5f);
    // fix up float rounding
    while ((by + 1) * (by + 2) / 2 <= t) by++;
    while (by * (by + 1) / 2 > t) by--;
    int bx = t - by * (by + 1) / 2;

    int tid = threadIdx.x, lane = tid & 31, w = tid >> 5;
    int wm = (w & 1) * 64, wn = (w >> 1) * 32;
    uint32_t sbase = smem_u32(smd);
    int z = blockIdx.z;
    int rowBase = by * 128, colBase = bx * 128;
    size_t qo = (size_t)z * Ss * Dd;
    const __nv_bfloat16* Qh = g_Qhi + qo + (size_t)rowBase * Dd;
    const __nv_bfloat16* Ql = g_Qlo + qo + (size_t)rowBase * Dd;
    const __nv_bfloat16* Kh = g_Khi + qo + (size_t)colBase * Dd;
    const __nv_bfloat16* Kl = g_Klo + qo + (size_t)colBase * Dd;
    float acc[4][4][4] = {};
    Seg seg[3] = { { Qh, Kh, Dd }, { Ql, Kh, Dd }, { Qh, Kl, Dd } };
    gemm_run(seg, Dd, Dd, sbase, acc, wm, wn, lane);

    float* C = g_scores + (size_t)z * Ss * Ss;
    int lr = lane >> 2, lc = (lane & 3) * 2;
#pragma unroll
    for (int mi = 0; mi < 4; mi++)
#pragma unroll
        for (int ni = 0; ni < 4; ni++)
#pragma unroll
            for (int half = 0; half < 2; half++) {
                int gr = rowBase + wm + mi * 16 + lr + half * 8;
                int col = colBase + wn + ni * 8 + lc;
                float2 v = make_float2(acc[mi][ni][half * 2] * SCALE,
                                       acc[mi][ni][half * 2 + 1] * SCALE);
                *(float2*)&C[(size_t)gr * Ss + col] = v;
            }
}

// ---------------- causal softmax; single pass, P written only up to Lpad ----------------
__global__ __launch_bounds__(256) void softmax_rows() {
    __shared__ float red[8];
    int gid = blockIdx.x;
    int z = gid >> 11;
    int i = gid & 2047;
    size_t ro = (size_t)z * Ss * Ss + (size_t)i * Ss;
    const float* row = g_scores + ro;
    int L = i + 1;
    int Lpad = ((i >> 7) + 1) << 7;   // = kEnd boundary that mma_pv consumes
    int tid = threadIdx.x;
    float v[8];
#pragma unroll
    for (int s = 0; s < 8; s++) {
        int j = tid + s * 256;
        v[s] = (j < L) ? row[j] : -3.4e38f;
    }
    float mx = v[0];
#pragma unroll
    for (int s = 1; s < 8; s++) mx = fmaxf(mx, v[s]);
#pragma unroll
    for (int o = 16; o; o >>= 1) mx = fmaxf(mx, __shfl_xor_sync(0xffffffffu, mx, o));
    if ((tid & 31) == 0) red[tid >> 5] = mx;
    __syncthreads();
    mx = red[0];
#pragma unroll
    for (int ww = 1; ww < 8; ww++) mx = fmaxf(mx, red[ww]);
    __syncthreads();
    float e[8];
    float sum = 0.f;
#pragma unroll
    for (int s = 0; s < 8; s++) {
        int j = tid + s * 256;
        e[s] = (j < L) ? __expf(v[s] - mx) : 0.0f;
        sum += e[s];
    }
#pragma unroll
    for (int o = 16; o; o >>= 1) sum += __shfl_xor_sync(0xffffffffu, sum, o);
    if ((tid & 31) == 0) red[tid >> 5] = sum;
    __syncthreads();
    sum = red[0];
#pragma unroll
    for (int ww = 1; ww < 8; ww++) sum += red[ww];
    float inv = 1.0f / sum;
#pragma unroll
    for (int s = 0; s < 8; s++) {
        int j = tid + s * 256;
        if (j < Lpad) {
            float p = e[s] * inv;
            __nv_bfloat16 hi, lo;
            split2(p, hi, lo);
            g_Phi[ro + j] = hi;
            g_Plo[ro + j] = lo;
        }
    }
}

// ---------------- Z = P V (causal K-limit) -> concat hi/lo ----------------
__global__ __launch_bounds__(256, 2) void mma_pv() {
    extern __shared__ __align__(16) char smd[];
    int tid = threadIdx.x, lane = tid & 31, w = tid >> 5;
    int wm = (w & 1) * 64, wn = (w >> 1) * 32;
    uint32_t sbase = smem_u32(smd);
    int z = blockIdx.z;
    int rowBase = blockIdx.y * 128, colBase = blockIdx.x * 128;
    int kEnd = rowBase + 128;
    const __nv_bfloat16* Ph = g_Phi + (size_t)z * Ss * Ss + (size_t)rowBase * Ss;
    const __nv_bfloat16* Pl = g_Plo + (size_t)z * Ss * Ss + (size_t)rowBase * Ss;
    const __nv_bfloat16* Vh = g_Vthi + (size_t)z * Dd * Ss + (size_t)colBase * Ss;
    const __nv_bfloat16* Vl = g_Vtlo + (size_t)z * Dd * Ss + (size_t)colBase * Ss;
    float acc[4][4][4] = {};
    Seg seg[3] = { { Ph, Vh, kEnd }, { Pl, Vh, kEnd }, { Ph, Vl, kEnd } };
    gemm_run(seg, Ss, Ss, sbase, acc, wm, wn, lane);

    int b = z / Hh, h = z % Hh;
    int lr = lane >> 2, lc = (lane & 3) * 2;
#pragma unroll
    for (int mi = 0; mi < 4; mi++)
#pragma unroll
        for (int ni = 0; ni < 4; ni++)
#pragma unroll
            for (int half = 0; half < 2; half++) {
                int sI = rowBase + wm + mi * 16 + lr + half * 8;
                int d = colBase + wn + ni * 8 + lc;
                __nv_bfloat16 h0, l0, h1, l1;
                split2(acc[mi][ni][half * 2], h0, l0);
                split2(acc[mi][ni][half * 2 + 1], h1, l1);
                size_t dst = ((size_t)(b * Ss + sI)) * Ee + h * Dd + d;
                g_Chi[dst] = h0; g_Clo[dst] = l0;
                g_Chi[dst + 1] = h1; g_Clo[dst + 1] = l1;
            }
}

// ---------------- out = concat @ Wo + bo ----------------
__global__ __launch_bounds__(256, 2) void mma_out(const float* __restrict__ bo,
                                                  float* __restrict__ out) {
    extern __shared__ __align__(16) char smd[];
    int tid = threadIdx.x, lane = tid & 31, w = tid >> 5;
    int wm = (w & 1) * 64, wn = (w >> 1) * 32;
    uint32_t sbase = smem_u32(smd);
    int rowBase = blockIdx.y * 128, colBase = blockIdx.x * 128;
    float acc[4][4][4] = {};
    Seg seg[3] = {
        { g_Chi + (size_t)rowBase * Ee, g_Wohi + (size_t)colBase * Ee, Ee },
        { g_Clo + (size_t)rowBase * Ee, g_Wohi + (size_t)colBase * Ee, Ee },
        { g_Chi + (size_t)rowBase * Ee, g_Wolo + (size_t)colBase * Ee, Ee } };
    gemm_run(seg, Ee, Ee, sbase, acc, wm, wn, lane);

    int lr = lane >> 2, lc = (lane & 3) * 2;
#pragma unroll
    for (int mi = 0; mi < 4; mi++)
#pragma unroll
        for (int ni = 0; ni < 4; ni++)
#pragma unroll
            for (int half = 0; half < 2; half++) {
                int gr = rowBase + wm + mi * 16 + lr + half * 8;
                int col = colBase + wn + ni * 8 + lc;
                float2 v = make_float2(acc[mi][ni][half * 2] + bo[col],
                                       acc[mi][ni][half * 2 + 1] + bo[col + 1]);
                *(float2*)&out[(size_t)gr * Ee + col] = v;
            }
}

// ---------------- launch ----------------
extern "C" void kernel_launch(void* const* d_in, const int* in_sizes, int n_in,
                              void* d_out, int out_size) {
    const float* Xk = (const float*)d_in[0];
    const float* Xv = (const float*)d_in[1];
    const float* Xq = (const float*)d_in[2];
    const float* WK = (const float*)d_in[3];
    const float* WV = (const float*)d_in[4];
    const float* WQ = (const float*)d_in[5];
    const float* Wo = (const float*)d_in[6];
    const float* bo = (const float*)d_in[7];
    float* out = (float*)d_out;

    // opt-in to >48KB dynamic smem (host-side attribute set; idempotent)
    cudaFuncSetAttribute(mma_proj, cudaFuncAttributeMaxDynamicSharedMemorySize, SMEM_TOTAL);
    cudaFuncSetAttribute(mma_scores, cudaFuncAttributeMaxDynamicSharedMemorySize, SMEM_TOTAL);
    cudaFuncSetAttribute(mma_pv, cudaFuncAttributeMaxDynamicSharedMemorySize, SMEM_TOTAL);
    cudaFuncSetAttribute(mma_out, cudaFuncAttributeMaxDynamicSharedMemorySize, SMEM_TOTAL);

    conv_inputs<<<(NE + 255) / 256, 256>>>(Xk, Xv, Xq);
    conv_weights<<<(EE + 255) / 256, 256>>>(WK, WV, WQ, Wo);

    dim3 gProj(Ee / 128, (Bb * Ss) / 128, 3);  // (6, 64, 3) — all projections in one launch
    mma_proj<<<gProj, 256, SMEM_TOTAL>>>();

    dim3 gSc(136, 1, BHh);                     // compact lower triangle: 136 tiles x 12
    mma_scores<<<gSc, 256, SMEM_TOTAL>>>();

    softmax_rows<<<BHh * Ss, 256>>>();

    dim3 gPv(Dd / 128, Ss / 128, BHh);         // (2, 16, 12)
    mma_pv<<<gPv, 256, SMEM_TOTAL>>>();

    dim3 gOut(Ee / 128, (Bb * Ss) / 128);      // (6, 64)
    mma_out<<<gOut, 256, SMEM_TOTAL>>>(bo, out);
}